// round 10
// baseline (speedup 1.0000x reference)
#include <cuda_runtime.h>
#include <math.h>

#define B 16
#define L 128
#define H 1024
#define V 50257
#define T (L-1)
#define BP (B/2)
#define NQ 12563             // quads per row; 4*NQ = 50252

typedef unsigned long long u64;

// ---- scratch (no allocations allowed) ----
__device__ float g_x0[B * H];
__device__ float g_h0[B * H];
__device__ float g_gi[B * 3 * H];
__device__ float g_gh[B * 3 * H];
__device__ float g_h1[B * H];
__device__ float g_logits[(size_t)B * V];
__device__ float g_m[B];
__device__ float g_l[B];

// grid barrier state (generation counter -> graph-replay safe)
__device__ volatile unsigned g_bar_gen;
__device__ unsigned g_bar_cnt;

__device__ __forceinline__ void grid_barrier(int nblocks) {
    __syncthreads();
    if (threadIdx.x == 0) {
        unsigned gen = g_bar_gen;
        __threadfence();
        if (atomicAdd(&g_bar_cnt, 1) == (unsigned)(nblocks - 1)) {
            g_bar_cnt = 0;
            __threadfence();
            g_bar_gen = gen + 1;
        } else {
            while (g_bar_gen == gen) { }
        }
    }
    __syncthreads();
}

// packed f32x2 FMA: d = a*b + d (2 MACs / SASS FFMA2)
__device__ __forceinline__ void ffma2(u64 &d, u64 a, u64 b) {
    asm("fma.rn.f32x2 %0, %1, %2, %0;" : "+l"(d) : "l"(a), "l"(b));
}
__device__ __forceinline__ u64 dup2(float f) {
    u64 r;
    asm("mov.b64 %0, {%1, %1};" : "=l"(r) : "f"(f));
    return r;
}
__device__ __forceinline__ float lo2(u64 a) { return __uint_as_float((unsigned)a); }
__device__ __forceinline__ float hi2(u64 a) { return __uint_as_float((unsigned)(a >> 32)); }

// XOR swizzle on u64 index: flips the 16B-granule bit on alternating 128B lines
__device__ __forceinline__ int swz(int i) { return i ^ (((i >> 4) & 1) << 1); }

// cp.async 16B, L2-only path (streaming)
__device__ __forceinline__ void cpasync16(unsigned dst, const void* src) {
    asm volatile("cp.async.cg.shared.global [%0], [%1], 16;" :: "r"(dst), "l"(src) : "memory");
}
__device__ __forceinline__ void cpcommit() {
    asm volatile("cp.async.commit_group;" ::: "memory");
}
template <int N>
__device__ __forceinline__ void cpwait() {
    asm volatile("cp.async.wait_group %0;" :: "n"(N) : "memory");
}

#define NB123 192   // fused front kernel: 192 blocks, all co-resident

// ---------------------------------------------------------------------------
// K123: fused k1 (embed+bridge) -> barrier -> k2 (gates GEMV) -> barrier ->
// k3 (GRU cell). One launch instead of three (tiny-kernel launch floors).
// ---------------------------------------------------------------------------
__global__ __launch_bounds__(256, 2)
void k123_front(const int* __restrict__ input,
                const float* __restrict__ hidden,
                const float* __restrict__ emb,
                const float* __restrict__ bridge_w,
                const float* __restrict__ bridge_b,
                const float* __restrict__ w_ih,
                const float* __restrict__ w_hh,
                const float* __restrict__ b_ih,
                const float* __restrict__ b_hh) {
    __shared__ float bw[L];
    __shared__ float part[4][64];
    int tid = threadIdx.x;
    if (tid < L) bw[tid] = bridge_w[tid];
    __syncthreads();

    // ---- phase A: x0 = relu(emb[tok]); h0 = bridge(hidden) ----
    int slot = tid & 63;
    int lc   = tid >> 6;
    for (int i0 = blockIdx.x * 64; i0 < B * H; i0 += NB123 * 64) {
        int i = i0 + slot;
        int b = i >> 10;
        int h = i & (H - 1);
        const float* hp = hidden + (size_t)b * L * H + (size_t)(lc * 32) * H + h;
        float a0 = 0.f, a1 = 0.f, a2 = 0.f, a3 = 0.f;
        #pragma unroll
        for (int l = 0; l < 32; l += 4) {
            a0 += hp[(l + 0) * H] * bw[lc * 32 + l + 0];
            a1 += hp[(l + 1) * H] * bw[lc * 32 + l + 1];
            a2 += hp[(l + 2) * H] * bw[lc * 32 + l + 2];
            a3 += hp[(l + 3) * H] * bw[lc * 32 + l + 3];
        }
        part[lc][slot] = (a0 + a1) + (a2 + a3);
        __syncthreads();
        if (lc == 0) {
            int tok = input[b * L];
            g_x0[i] = fmaxf(emb[(size_t)tok * H + h], 0.0f);
            g_h0[i] = (part[0][slot] + part[1][slot]) +
                      (part[2][slot] + part[3][slot]) + bridge_b[0];
        }
        __syncthreads();
    }

    grid_barrier(NB123);

    // ---- phase B: gi = x0 @ w_ih^T + b_ih ; gh = h0 @ w_hh^T + b_hh ----
    {
        int warp = tid >> 5;
        int lane = tid & 31;
        int j0 = (blockIdx.x * 8 + warp) * 2;

        float ai0[B], ai1[B], ah0[B], ah1[B];
        #pragma unroll
        for (int b = 0; b < B; b++) { ai0[b] = ai1[b] = ah0[b] = ah1[b] = 0.f; }

        for (int i = 0; i < 8; i++) {
            int k = i * 128 + lane * 4;
            float4 wi0 = *(const float4*)(w_ih + (size_t)(j0 + 0) * H + k);
            float4 wi1 = *(const float4*)(w_ih + (size_t)(j0 + 1) * H + k);
            float4 wh0 = *(const float4*)(w_hh + (size_t)(j0 + 0) * H + k);
            float4 wh1 = *(const float4*)(w_hh + (size_t)(j0 + 1) * H + k);
            #pragma unroll
            for (int b = 0; b < B; b++) {
                float4 x = *(const float4*)(g_x0 + b * H + k);
                float4 h = *(const float4*)(g_h0 + b * H + k);
                ai0[b] += wi0.x * x.x + wi0.y * x.y + wi0.z * x.z + wi0.w * x.w;
                ai1[b] += wi1.x * x.x + wi1.y * x.y + wi1.z * x.z + wi1.w * x.w;
                ah0[b] += wh0.x * h.x + wh0.y * h.y + wh0.z * h.z + wh0.w * h.w;
                ah1[b] += wh1.x * h.x + wh1.y * h.y + wh1.z * h.z + wh1.w * h.w;
            }
        }

        #pragma unroll
        for (int b = 0; b < B; b++) {
            #pragma unroll
            for (int o = 16; o; o >>= 1) {
                ai0[b] += __shfl_xor_sync(0xffffffffu, ai0[b], o);
                ai1[b] += __shfl_xor_sync(0xffffffffu, ai1[b], o);
                ah0[b] += __shfl_xor_sync(0xffffffffu, ah0[b], o);
                ah1[b] += __shfl_xor_sync(0xffffffffu, ah1[b], o);
            }
        }

        if (lane == 0) {
            float bi0 = b_ih[j0], bi1 = b_ih[j0 + 1];
            float bh0 = b_hh[j0], bh1 = b_hh[j0 + 1];
            #pragma unroll
            for (int b = 0; b < B; b++) {
                g_gi[b * 3 * H + j0]     = ai0[b] + bi0;
                g_gi[b * 3 * H + j0 + 1] = ai1[b] + bi1;
                g_gh[b * 3 * H + j0]     = ah0[b] + bh0;
                g_gh[b * 3 * H + j0 + 1] = ah1[b] + bh1;
            }
        }
    }

    grid_barrier(NB123);

    // ---- phase C: GRU cell -> h1 ----
    {
        int gtid = blockIdx.x * 256 + tid;
        if (gtid < B * H) {
            int b = gtid >> 10;
            int h = gtid & (H - 1);
            int base = b * 3 * H + h;
            float ir = g_gi[base], iz = g_gi[base + H], in_ = g_gi[base + 2 * H];
            float hr = g_gh[base], hz = g_gh[base + H], hn  = g_gh[base + 2 * H];
            float r = 1.f / (1.f + expf(-(ir + hr)));
            float z = 1.f / (1.f + expf(-(iz + hz)));
            float n = tanhf(in_ + r * hn);
            g_h1[gtid] = (1.f - z) * n + z * g_h0[gtid];
        }
    }
}

// ---------------------------------------------------------------------------
// K4: logits[b,v] = h1[b,:] . proj_w[v,:] + proj_b[v]
// Batch-packed f32x2 + swizzled smem h1 + cp.async double-buffered proj_w.
// (round-8/9 committed version, unchanged)
// ---------------------------------------------------------------------------
__global__ __launch_bounds__(256, 2)
void k4_proj(const float* __restrict__ proj_w,
             const float* __restrict__ proj_b) {
    extern __shared__ char smem_raw[];
    u64*  hs = (u64*)smem_raw;                    // 64KB, swizzled
    char* pf = smem_raw + 65536;                  // 32KB staging

    for (int i = threadIdx.x; i < BP * H; i += 256) {
        int bp = i >> 10;
        int k  = i & (H - 1);
        unsigned lo = __float_as_uint(g_h1[(2 * bp) * H + k]);
        unsigned hi = __float_as_uint(g_h1[(2 * bp + 1) * H + k]);
        hs[swz(i)] = ((u64)hi << 32) | (u64)lo;
    }
    __syncthreads();

    int warp = threadIdx.x >> 5;
    int lane = threadIdx.x & 31;
    int v0 = (blockIdx.x * 8 + warp) * 4;
    if (v0 >= V) return;

    int r1 = min(v0 + 1, V - 1);
    int r2 = min(v0 + 2, V - 1);
    int r3 = min(v0 + 3, V - 1);
    const char* w0 = (const char*)(proj_w + (size_t)v0 * H);
    const char* w1 = (const char*)(proj_w + (size_t)r1 * H);
    const char* w2 = (const char*)(proj_w + (size_t)r2 * H);
    const char* w3 = (const char*)(proj_w + (size_t)r3 * H);

    char* pfw = pf + warp * 4096 + lane * 16;
    unsigned pfw_s = (unsigned)__cvta_generic_to_shared(pfw);

    u64 a0[BP], a1[BP], a2[BP], a3[BP];
    #pragma unroll
    for (int bp = 0; bp < BP; bp++) { a0[bp] = a1[bp] = a2[bp] = a3[bp] = 0ull; }

    {
        int off = lane * 16;
        cpasync16(pfw_s + 0 * 2048 + 0 * 512, w0 + off);
        cpasync16(pfw_s + 0 * 2048 + 1 * 512, w1 + off);
        cpasync16(pfw_s + 0 * 2048 + 2 * 512, w2 + off);
        cpasync16(pfw_s + 0 * 2048 + 3 * 512, w3 + off);
        cpcommit();
        cpasync16(pfw_s + 1 * 2048 + 0 * 512, w0 + 512 + off);
        cpasync16(pfw_s + 1 * 2048 + 1 * 512, w1 + 512 + off);
        cpasync16(pfw_s + 1 * 2048 + 2 * 512, w2 + 512 + off);
        cpasync16(pfw_s + 1 * 2048 + 3 * 512, w3 + 512 + off);
        cpcommit();
    }

    #pragma unroll
    for (int i = 0; i < 8; i++) {
        const int buf = i & 1;
        if (i < 6) cpwait<1>(); else cpwait<0>();

        const char* pb = pf + warp * 4096 + buf * 2048 + lane * 16;
        float4 p0 = *(const float4*)(pb + 0 * 512);
        float4 p1 = *(const float4*)(pb + 1 * 512);
        float4 p2 = *(const float4*)(pb + 2 * 512);
        float4 p3 = *(const float4*)(pb + 3 * 512);
        u64 q0x = dup2(p0.x), q0y = dup2(p0.y), q0z = dup2(p0.z), q0w = dup2(p0.w);
        u64 q1x = dup2(p1.x), q1y = dup2(p1.y), q1z = dup2(p1.z), q1w = dup2(p1.w);
        u64 q2x = dup2(p2.x), q2y = dup2(p2.y), q2z = dup2(p2.z), q2w = dup2(p2.w);
        u64 q3x = dup2(p3.x), q3y = dup2(p3.y), q3z = dup2(p3.z), q3w = dup2(p3.w);

        if (i < 6) {
            int off = (i + 2) * 512 + lane * 16;
            unsigned d = pfw_s + buf * 2048;
            cpasync16(d + 0 * 512, w0 + off);
            cpasync16(d + 1 * 512, w1 + off);
            cpasync16(d + 2 * 512, w2 + off);
            cpasync16(d + 3 * 512, w3 + off);
            cpcommit();
        }

        int kq = i * 32 + lane;
        #pragma unroll
        for (int bp = 0; bp < BP; bp++) {
            int idx = bp * 1024 + kq * 4;
            int f   = ((idx >> 4) & 1) << 1;
            ulonglong2 xa = *(const ulonglong2*)(hs + (idx ^ f));
            ulonglong2 xb = *(const ulonglong2*)(hs + ((idx + 2) ^ f));
            ffma2(a0[bp], q0x, xa.x); ffma2(a0[bp], q0y, xa.y);
            ffma2(a0[bp], q0z, xb.x); ffma2(a0[bp], q0w, xb.y);
            ffma2(a1[bp], q1x, xa.x); ffma2(a1[bp], q1y, xa.y);
            ffma2(a1[bp], q1z, xb.x); ffma2(a1[bp], q1w, xb.y);
            ffma2(a2[bp], q2x, xa.x); ffma2(a2[bp], q2y, xa.y);
            ffma2(a2[bp], q2z, xb.x); ffma2(a2[bp], q2w, xb.y);
            ffma2(a3[bp], q3x, xa.x); ffma2(a3[bp], q3y, xa.y);
            ffma2(a3[bp], q3z, xb.x); ffma2(a3[bp], q3w, xb.y);
        }
    }

    float pb0 = proj_b[v0];
    float pb1 = proj_b[r1];
    float pb2 = proj_b[r2];
    float pb3 = proj_b[r3];

    #pragma unroll
    for (int bp = 0; bp < BP; bp++) {
        float s0a = lo2(a0[bp]), s0b = hi2(a0[bp]);
        float s1a = lo2(a1[bp]), s1b = hi2(a1[bp]);
        float s2a = lo2(a2[bp]), s2b = hi2(a2[bp]);
        float s3a = lo2(a3[bp]), s3b = hi2(a3[bp]);
        #pragma unroll
        for (int o = 16; o; o >>= 1) {
            s0a += __shfl_xor_sync(0xffffffffu, s0a, o);
            s0b += __shfl_xor_sync(0xffffffffu, s0b, o);
            s1a += __shfl_xor_sync(0xffffffffu, s1a, o);
            s1b += __shfl_xor_sync(0xffffffffu, s1b, o);
            s2a += __shfl_xor_sync(0xffffffffu, s2a, o);
            s2b += __shfl_xor_sync(0xffffffffu, s2b, o);
            s3a += __shfl_xor_sync(0xffffffffu, s3a, o);
            s3b += __shfl_xor_sync(0xffffffffu, s3b, o);
        }
        if (lane == 0) {
            float* lga = g_logits + (size_t)(2 * bp) * V;
            float* lgb = g_logits + (size_t)(2 * bp + 1) * V;
            lga[v0] = s0a + pb0;  lgb[v0] = s0b + pb0;
            if (v0 + 1 < V) { lga[v0 + 1] = s1a + pb1;  lgb[v0 + 1] = s1b + pb1; }
            if (v0 + 2 < V) { lga[v0 + 2] = s2a + pb2;  lgb[v0 + 2] = s2b + pb2; }
            if (v0 + 3 < V) { lga[v0 + 3] = s3a + pb3;  lgb[v0 + 3] = s3b + pb3; }
        }
    }
}

// ---------------------------------------------------------------------------
// K5: per-batch max and log-sum-exp over V (logits hot in L2), 1024 threads
// ---------------------------------------------------------------------------
__global__ void k5_lse() {
    int b = blockIdx.x;
    __shared__ float red[1024];
    const float* lg = g_logits + (size_t)b * V;

    float m = -1e30f;
    for (int v = threadIdx.x; v < V; v += 1024) m = fmaxf(m, lg[v]);
    red[threadIdx.x] = m;
    __syncthreads();
    for (int s = 512; s; s >>= 1) {
        if (threadIdx.x < s) red[threadIdx.x] = fmaxf(red[threadIdx.x], red[threadIdx.x + s]);
        __syncthreads();
    }
    m = red[0];
    __syncthreads();

    float sum = 0.f;
    for (int v = threadIdx.x; v < V; v += 1024) sum += expf(lg[v] - m);
    red[threadIdx.x] = sum;
    __syncthreads();
    for (int s = 512; s; s >>= 1) {
        if (threadIdx.x < s) red[threadIdx.x] += red[threadIdx.x + s];
        __syncthreads();
    }
    if (threadIdx.x == 0) { g_m[b] = m; g_l[b] = logf(red[0]); }
}

// ---------------------------------------------------------------------------
// K6: out[b,t,v] = logits[b,v] - m[b] - lse[b], broadcast over t, with
// alignment-shifted STG.128 quads. Row base r=(b*127+t) has r*V ≡ r (mod 4),
// so quads at v = 4j + s with s = (4 - (r&3)) & 3 are 16B-aligned. Thread j
// precomputes the 4 shift variants from 7 logits and runs four stride-4
// t-loops. Thread j==NQ covers the <=5 leftover scalars per row.
// ---------------------------------------------------------------------------
__global__ void k6_out(float* __restrict__ out) {
    int j = blockIdx.x * 256 + threadIdx.x;
    int b = blockIdx.y;
    if (j > NQ) return;
    float sub = g_m[b] + g_l[b];
    const float* lg = g_logits + (size_t)b * V;
    float* ob = out + (size_t)b * T * V;

    if (j < NQ) {
        float q0 = lg[4 * j + 0] - sub, q1 = lg[4 * j + 1] - sub;
        float q2 = lg[4 * j + 2] - sub, q3 = lg[4 * j + 3] - sub;
        float q4 = lg[4 * j + 4] - sub, q5 = lg[4 * j + 5] - sub;
        float q6 = lg[4 * j + 6] - sub;
        float4 v0 = make_float4(q0, q1, q2, q3);   // s=0 (r%4==0)
        float4 v3 = make_float4(q3, q4, q5, q6);   // s=3 (r%4==1)
        float4 v2 = make_float4(q2, q3, q4, q5);   // s=2 (r%4==2)
        float4 v1 = make_float4(q1, q2, q3, q4);   // s=1 (r%4==3)

        // r = b*127 + t ≡ 3b + t (mod 4); r≡c ⇔ t ≡ c + b (mod 4)
        int t0;
        t0 = (0 + b) & 3;
        #pragma unroll 4
        for (int t = t0; t < T; t += 4) *(float4*)(ob + (size_t)t * V + 4 * j + 0) = v0;
        t0 = (1 + b) & 3;
        #pragma unroll 4
        for (int t = t0; t < T; t += 4) *(float4*)(ob + (size_t)t * V + 4 * j + 3) = v3;
        t0 = (2 + b) & 3;
        #pragma unroll 4
        for (int t = t0; t < T; t += 4) *(float4*)(ob + (size_t)t * V + 4 * j + 2) = v2;
        t0 = (3 + b) & 3;
        #pragma unroll 4
        for (int t = t0; t < T; t += 4) *(float4*)(ob + (size_t)t * V + 4 * j + 1) = v1;
    } else {
        // leftovers: head v in [0,s), tail v in [4*NQ+s, V)
        float h0 = lg[0] - sub, h1 = lg[1] - sub, h2 = lg[2] - sub;
        float e0 = lg[4 * NQ + 0] - sub, e1 = lg[4 * NQ + 1] - sub;
        float e2 = lg[4 * NQ + 2] - sub, e3 = lg[4 * NQ + 3] - sub;
        float e4 = lg[4 * NQ + 4] - sub;
        for (int t = 0; t < T; t++) {
            int c = (3 * b + t) & 3;        // r & 3
            int s = (4 - c) & 3;
            float* row = ob + (size_t)t * V;
            if (s > 0) row[0] = h0;
            if (s > 1) row[1] = h1;
            if (s > 2) row[2] = h2;
            if (s == 0) row[4 * NQ + 0] = e0;
            if (s <= 1) row[4 * NQ + 1] = e1;
            if (s <= 2) row[4 * NQ + 2] = e2;
            if (s <= 3) row[4 * NQ + 3] = e3;
            row[4 * NQ + 4] = e4;
        }
    }
}

// ---------------------------------------------------------------------------
extern "C" void kernel_launch(void* const* d_in, const int* in_sizes, int n_in,
                              void* d_out, int out_size) {
    const int*   input    = (const int*)d_in[0];
    const float* hidden   = (const float*)d_in[1];
    const float* emb      = (const float*)d_in[2];
    const float* bridge_w = (const float*)d_in[3];
    const float* bridge_b = (const float*)d_in[4];
    const float* w_ih     = (const float*)d_in[5];
    const float* w_hh     = (const float*)d_in[6];
    const float* b_ih     = (const float*)d_in[7];
    const float* b_hh     = (const float*)d_in[8];
    const float* proj_w   = (const float*)d_in[9];
    const float* proj_b   = (const float*)d_in[10];
    float* out = (float*)d_out;

    const int k4_smem = 65536 + 32768;
    cudaFuncSetAttribute(k4_proj, cudaFuncAttributeMaxDynamicSharedMemorySize,
                         k4_smem);

    k123_front<<<NB123, 256>>>(input, hidden, emb, bridge_w, bridge_b,
                               w_ih, w_hh, b_ih, b_hh);
    int blocks4 = (V + 31) / 32;
    k4_proj<<<blocks4, 256, k4_smem>>>(proj_w, proj_b);
    k5_lse<<<B, 1024>>>();
    dim3 g6((NQ + 1 + 255) / 256, B);
    k6_out<<<g6, 256>>>(out);
}

// round 12
// speedup vs baseline: 1.0127x; 1.0127x over previous
#include <cuda_runtime.h>
#include <math.h>

#define B 16
#define L 128
#define H 1024
#define V 50257
#define T (L-1)
#define BP (B/2)
#define NQ 12563             // quads per row; 4*NQ = 50252
#define NB123 192
#define NB56 800             // 50 x-blocks * 16 batches, co-resident (<=888)

typedef unsigned long long u64;

// ---- scratch (no allocations allowed) ----
__device__ float g_x0[B * H];
__device__ float g_h0[B * H];
__device__ float g_gi[B * 3 * H];
__device__ float g_gh[B * 3 * H];
__device__ float g_h1[B * H];
__device__ float g_logits[(size_t)B * V];
__device__ float g_sum[B];

// grid barrier state (generation counter -> graph-replay safe)
__device__ volatile unsigned g_bar_gen;
__device__ unsigned g_bar_cnt;

__device__ __forceinline__ void grid_barrier(int nblocks) {
    __syncthreads();
    if (threadIdx.x == 0) {
        unsigned gen = g_bar_gen;
        __threadfence();
        if (atomicAdd(&g_bar_cnt, 1) == (unsigned)(nblocks - 1)) {
            g_bar_cnt = 0;
            __threadfence();
            g_bar_gen = gen + 1;
        } else {
            while (g_bar_gen == gen) { }
        }
    }
    __syncthreads();
}

// packed f32x2 FMA: d = a*b + d (2 MACs / SASS FFMA2)
__device__ __forceinline__ void ffma2(u64 &d, u64 a, u64 b) {
    asm("fma.rn.f32x2 %0, %1, %2, %0;" : "+l"(d) : "l"(a), "l"(b));
}
__device__ __forceinline__ u64 dup2(float f) {
    u64 r;
    asm("mov.b64 %0, {%1, %1};" : "=l"(r) : "f"(f));
    return r;
}
__device__ __forceinline__ float lo2(u64 a) { return __uint_as_float((unsigned)a); }
__device__ __forceinline__ float hi2(u64 a) { return __uint_as_float((unsigned)(a >> 32)); }

// XOR swizzle on u64 index: flips the 16B-granule bit on alternating 128B lines
__device__ __forceinline__ int swz(int i) { return i ^ (((i >> 4) & 1) << 1); }

// cp.async 16B, L2-only path (streaming)
__device__ __forceinline__ void cpasync16(unsigned dst, const void* src) {
    asm volatile("cp.async.cg.shared.global [%0], [%1], 16;" :: "r"(dst), "l"(src) : "memory");
}
__device__ __forceinline__ void cpcommit() {
    asm volatile("cp.async.commit_group;" ::: "memory");
}
template <int N>
__device__ __forceinline__ void cpwait() {
    asm volatile("cp.async.wait_group %0;" :: "n"(N) : "memory");
}

// ---------------------------------------------------------------------------
// K123: fused embed+bridge -> barrier -> gates GEMV -> barrier -> GRU cell.
// Also zeroes g_sum for the k56 atomics (every call -> replay-safe).
// ---------------------------------------------------------------------------
__global__ __launch_bounds__(256, 2)
void k123_front(const int* __restrict__ input,
                const float* __restrict__ hidden,
                const float* __restrict__ emb,
                const float* __restrict__ bridge_w,
                const float* __restrict__ bridge_b,
                const float* __restrict__ w_ih,
                const float* __restrict__ w_hh,
                const float* __restrict__ b_ih,
                const float* __restrict__ b_hh) {
    __shared__ float bw[L];
    __shared__ float part[4][64];
    int tid = threadIdx.x;
    if (tid < L) bw[tid] = bridge_w[tid];
    if (blockIdx.x == 0 && tid < B) g_sum[tid] = 0.f;
    __syncthreads();

    // ---- phase A: x0 = relu(emb[tok]); h0 = bridge(hidden) ----
    int slot = tid & 63;
    int lc   = tid >> 6;
    for (int i0 = blockIdx.x * 64; i0 < B * H; i0 += NB123 * 64) {
        int i = i0 + slot;
        int b = i >> 10;
        int h = i & (H - 1);
        const float* hp = hidden + (size_t)b * L * H + (size_t)(lc * 32) * H + h;
        float a0 = 0.f, a1 = 0.f, a2 = 0.f, a3 = 0.f;
        #pragma unroll
        for (int l = 0; l < 32; l += 4) {
            a0 += hp[(l + 0) * H] * bw[lc * 32 + l + 0];
            a1 += hp[(l + 1) * H] * bw[lc * 32 + l + 1];
            a2 += hp[(l + 2) * H] * bw[lc * 32 + l + 2];
            a3 += hp[(l + 3) * H] * bw[lc * 32 + l + 3];
        }
        part[lc][slot] = (a0 + a1) + (a2 + a3);
        __syncthreads();
        if (lc == 0) {
            int tok = input[b * L];
            g_x0[i] = fmaxf(emb[(size_t)tok * H + h], 0.0f);
            g_h0[i] = (part[0][slot] + part[1][slot]) +
                      (part[2][slot] + part[3][slot]) + bridge_b[0];
        }
        __syncthreads();
    }

    grid_barrier(NB123);

    // ---- phase B: gi = x0 @ w_ih^T + b_ih ; gh = h0 @ w_hh^T + b_hh ----
    {
        int warp = tid >> 5;
        int lane = tid & 31;
        int j0 = (blockIdx.x * 8 + warp) * 2;

        float ai0[B], ai1[B], ah0[B], ah1[B];
        #pragma unroll
        for (int b = 0; b < B; b++) { ai0[b] = ai1[b] = ah0[b] = ah1[b] = 0.f; }

        for (int i = 0; i < 8; i++) {
            int k = i * 128 + lane * 4;
            float4 wi0 = *(const float4*)(w_ih + (size_t)(j0 + 0) * H + k);
            float4 wi1 = *(const float4*)(w_ih + (size_t)(j0 + 1) * H + k);
            float4 wh0 = *(const float4*)(w_hh + (size_t)(j0 + 0) * H + k);
            float4 wh1 = *(const float4*)(w_hh + (size_t)(j0 + 1) * H + k);
            #pragma unroll
            for (int b = 0; b < B; b++) {
                float4 x = *(const float4*)(g_x0 + b * H + k);
                float4 h = *(const float4*)(g_h0 + b * H + k);
                ai0[b] += wi0.x * x.x + wi0.y * x.y + wi0.z * x.z + wi0.w * x.w;
                ai1[b] += wi1.x * x.x + wi1.y * x.y + wi1.z * x.z + wi1.w * x.w;
                ah0[b] += wh0.x * h.x + wh0.y * h.y + wh0.z * h.z + wh0.w * h.w;
                ah1[b] += wh1.x * h.x + wh1.y * h.y + wh1.z * h.z + wh1.w * h.w;
            }
        }

        #pragma unroll
        for (int b = 0; b < B; b++) {
            #pragma unroll
            for (int o = 16; o; o >>= 1) {
                ai0[b] += __shfl_xor_sync(0xffffffffu, ai0[b], o);
                ai1[b] += __shfl_xor_sync(0xffffffffu, ai1[b], o);
                ah0[b] += __shfl_xor_sync(0xffffffffu, ah0[b], o);
                ah1[b] += __shfl_xor_sync(0xffffffffu, ah1[b], o);
            }
        }

        if (lane == 0) {
            float bi0 = b_ih[j0], bi1 = b_ih[j0 + 1];
            float bh0 = b_hh[j0], bh1 = b_hh[j0 + 1];
            #pragma unroll
            for (int b = 0; b < B; b++) {
                g_gi[b * 3 * H + j0]     = ai0[b] + bi0;
                g_gi[b * 3 * H + j0 + 1] = ai1[b] + bi1;
                g_gh[b * 3 * H + j0]     = ah0[b] + bh0;
                g_gh[b * 3 * H + j0 + 1] = ah1[b] + bh1;
            }
        }
    }

    grid_barrier(NB123);

    // ---- phase C: GRU cell -> h1 ----
    {
        int gtid = blockIdx.x * 256 + tid;
        if (gtid < B * H) {
            int b = gtid >> 10;
            int h = gtid & (H - 1);
            int base = b * 3 * H + h;
            float ir = g_gi[base], iz = g_gi[base + H], in_ = g_gi[base + 2 * H];
            float hr = g_gh[base], hz = g_gh[base + H], hn  = g_gh[base + 2 * H];
            float r = 1.f / (1.f + expf(-(ir + hr)));
            float z = 1.f / (1.f + expf(-(iz + hz)));
            float n = tanhf(in_ + r * hn);
            g_h1[gtid] = (1.f - z) * n + z * g_h0[gtid];
        }
    }
}

// ---------------------------------------------------------------------------
// K4: logits[b,v] = h1[b,:] . proj_w[v,:] + proj_b[v]
// Batch-packed f32x2 + swizzled smem h1 + cp.async double-buffered proj_w.
// (committed version, unchanged)
// ---------------------------------------------------------------------------
__global__ __launch_bounds__(256, 2)
void k4_proj(const float* __restrict__ proj_w,
             const float* __restrict__ proj_b) {
    extern __shared__ char smem_raw[];
    u64*  hs = (u64*)smem_raw;                    // 64KB, swizzled
    char* pf = smem_raw + 65536;                  // 32KB staging

    for (int i = threadIdx.x; i < BP * H; i += 256) {
        int bp = i >> 10;
        int k  = i & (H - 1);
        unsigned lo = __float_as_uint(g_h1[(2 * bp) * H + k]);
        unsigned hi = __float_as_uint(g_h1[(2 * bp + 1) * H + k]);
        hs[swz(i)] = ((u64)hi << 32) | (u64)lo;
    }
    __syncthreads();

    int warp = threadIdx.x >> 5;
    int lane = threadIdx.x & 31;
    int v0 = (blockIdx.x * 8 + warp) * 4;
    if (v0 >= V) return;

    int r1 = min(v0 + 1, V - 1);
    int r2 = min(v0 + 2, V - 1);
    int r3 = min(v0 + 3, V - 1);
    const char* w0 = (const char*)(proj_w + (size_t)v0 * H);
    const char* w1 = (const char*)(proj_w + (size_t)r1 * H);
    const char* w2 = (const char*)(proj_w + (size_t)r2 * H);
    const char* w3 = (const char*)(proj_w + (size_t)r3 * H);

    char* pfw = pf + warp * 4096 + lane * 16;
    unsigned pfw_s = (unsigned)__cvta_generic_to_shared(pfw);

    u64 a0[BP], a1[BP], a2[BP], a3[BP];
    #pragma unroll
    for (int bp = 0; bp < BP; bp++) { a0[bp] = a1[bp] = a2[bp] = a3[bp] = 0ull; }

    {
        int off = lane * 16;
        cpasync16(pfw_s + 0 * 2048 + 0 * 512, w0 + off);
        cpasync16(pfw_s + 0 * 2048 + 1 * 512, w1 + off);
        cpasync16(pfw_s + 0 * 2048 + 2 * 512, w2 + off);
        cpasync16(pfw_s + 0 * 2048 + 3 * 512, w3 + off);
        cpcommit();
        cpasync16(pfw_s + 1 * 2048 + 0 * 512, w0 + 512 + off);
        cpasync16(pfw_s + 1 * 2048 + 1 * 512, w1 + 512 + off);
        cpasync16(pfw_s + 1 * 2048 + 2 * 512, w2 + 512 + off);
        cpasync16(pfw_s + 1 * 2048 + 3 * 512, w3 + 512 + off);
        cpcommit();
    }

    #pragma unroll
    for (int i = 0; i < 8; i++) {
        const int buf = i & 1;
        if (i < 6) cpwait<1>(); else cpwait<0>();

        const char* pb = pf + warp * 4096 + buf * 2048 + lane * 16;
        float4 p0 = *(const float4*)(pb + 0 * 512);
        float4 p1 = *(const float4*)(pb + 1 * 512);
        float4 p2 = *(const float4*)(pb + 2 * 512);
        float4 p3 = *(const float4*)(pb + 3 * 512);
        u64 q0x = dup2(p0.x), q0y = dup2(p0.y), q0z = dup2(p0.z), q0w = dup2(p0.w);
        u64 q1x = dup2(p1.x), q1y = dup2(p1.y), q1z = dup2(p1.z), q1w = dup2(p1.w);
        u64 q2x = dup2(p2.x), q2y = dup2(p2.y), q2z = dup2(p2.z), q2w = dup2(p2.w);
        u64 q3x = dup2(p3.x), q3y = dup2(p3.y), q3z = dup2(p3.z), q3w = dup2(p3.w);

        if (i < 6) {
            int off = (i + 2) * 512 + lane * 16;
            unsigned d = pfw_s + buf * 2048;
            cpasync16(d + 0 * 512, w0 + off);
            cpasync16(d + 1 * 512, w1 + off);
            cpasync16(d + 2 * 512, w2 + off);
            cpasync16(d + 3 * 512, w3 + off);
            cpcommit();
        }

        int kq = i * 32 + lane;
        #pragma unroll
        for (int bp = 0; bp < BP; bp++) {
            int idx = bp * 1024 + kq * 4;
            int f   = ((idx >> 4) & 1) << 1;
            ulonglong2 xa = *(const ulonglong2*)(hs + (idx ^ f));
            ulonglong2 xb = *(const ulonglong2*)(hs + ((idx + 2) ^ f));
            ffma2(a0[bp], q0x, xa.x); ffma2(a0[bp], q0y, xa.y);
            ffma2(a0[bp], q0z, xb.x); ffma2(a0[bp], q0w, xb.y);
            ffma2(a1[bp], q1x, xa.x); ffma2(a1[bp], q1y, xa.y);
            ffma2(a1[bp], q1z, xb.x); ffma2(a1[bp], q1w, xb.y);
            ffma2(a2[bp], q2x, xa.x); ffma2(a2[bp], q2y, xa.y);
            ffma2(a2[bp], q2z, xb.x); ffma2(a2[bp], q2w, xb.y);
            ffma2(a3[bp], q3x, xa.x); ffma2(a3[bp], q3y, xa.y);
            ffma2(a3[bp], q3z, xb.x); ffma2(a3[bp], q3w, xb.y);
        }
    }

    float pb0 = proj_b[v0];
    float pb1 = proj_b[r1];
    float pb2 = proj_b[r2];
    float pb3 = proj_b[r3];

    #pragma unroll
    for (int bp = 0; bp < BP; bp++) {
        float s0a = lo2(a0[bp]), s0b = hi2(a0[bp]);
        float s1a = lo2(a1[bp]), s1b = hi2(a1[bp]);
        float s2a = lo2(a2[bp]), s2b = hi2(a2[bp]);
        float s3a = lo2(a3[bp]), s3b = hi2(a3[bp]);
        #pragma unroll
        for (int o = 16; o; o >>= 1) {
            s0a += __shfl_xor_sync(0xffffffffu, s0a, o);
            s0b += __shfl_xor_sync(0xffffffffu, s0b, o);
            s1a += __shfl_xor_sync(0xffffffffu, s1a, o);
            s1b += __shfl_xor_sync(0xffffffffu, s1b, o);
            s2a += __shfl_xor_sync(0xffffffffu, s2a, o);
            s2b += __shfl_xor_sync(0xffffffffu, s2b, o);
            s3a += __shfl_xor_sync(0xffffffffu, s3a, o);
            s3b += __shfl_xor_sync(0xffffffffu, s3b, o);
        }
        if (lane == 0) {
            float* lga = g_logits + (size_t)(2 * bp) * V;
            float* lgb = g_logits + (size_t)(2 * bp + 1) * V;
            lga[v0] = s0a + pb0;  lgb[v0] = s0b + pb0;
            if (v0 + 1 < V) { lga[v0 + 1] = s1a + pb1;  lgb[v0 + 1] = s1b + pb1; }
            if (v0 + 2 < V) { lga[v0 + 2] = s2a + pb2;  lgb[v0 + 2] = s2b + pb2; }
            if (v0 + 3 < V) { lga[v0 + 3] = s3a + pb3;  lgb[v0 + 3] = s3b + pb3; }
        }
    }
}

// ---------------------------------------------------------------------------
// K56: fused log-sum-exp + broadcast output.
// No max-subtraction needed (|logit| small): sub = log(sum exp(logit)).
// Each block sums exp over its own logits (loaded once, reused for stores),
// atomicAdd -> g_sum[b], grid barrier (800 co-resident blocks), then
// alignment-shifted STG.128 quads with streaming (.cs) stores.
// ---------------------------------------------------------------------------
__global__ __launch_bounds__(256, 6)
void k56_out(float* __restrict__ out) {
    __shared__ float wsum[8];
    int j = blockIdx.x * 256 + threadIdx.x;
    int b = blockIdx.y;
    const float* lg = g_logits + (size_t)b * V;

    float q0 = 0, q1 = 0, q2 = 0, q3 = 0, q4 = 0, q5 = 0, q6 = 0;
    float h0 = 0, h1 = 0, h2 = 0, e0 = 0, e1 = 0, e2 = 0, e3 = 0, e4 = 0;
    float s = 0.f;
    if (j < NQ) {
        q0 = lg[4 * j + 0]; q1 = lg[4 * j + 1];
        q2 = lg[4 * j + 2]; q3 = lg[4 * j + 3];
        q4 = lg[4 * j + 4]; q5 = lg[4 * j + 5];
        q6 = lg[4 * j + 6];
        s = (expf(q0) + expf(q1)) + (expf(q2) + expf(q3));
    } else if (j == NQ) {
        h0 = lg[0]; h1 = lg[1]; h2 = lg[2];
        e0 = lg[4 * NQ + 0]; e1 = lg[4 * NQ + 1]; e2 = lg[4 * NQ + 2];
        e3 = lg[4 * NQ + 3]; e4 = lg[4 * NQ + 4];
        s = (expf(e0) + expf(e1)) + (expf(e2) + expf(e3)) + expf(e4);
    }

    #pragma unroll
    for (int o = 16; o; o >>= 1) s += __shfl_xor_sync(0xffffffffu, s, o);
    if ((threadIdx.x & 31) == 0) wsum[threadIdx.x >> 5] = s;
    __syncthreads();
    if (threadIdx.x == 0) {
        float t = 0.f;
        #pragma unroll
        for (int w = 0; w < 8; w++) t += wsum[w];
        atomicAdd(&g_sum[b], t);
    }

    grid_barrier(NB56);

    float sub = logf(__ldcg((const float*)&g_sum[b]));
    float* ob = out + (size_t)b * T * V;

    if (j < NQ) {
        q0 -= sub; q1 -= sub; q2 -= sub; q3 -= sub;
        q4 -= sub; q5 -= sub; q6 -= sub;
        float4 v0 = make_float4(q0, q1, q2, q3);   // s=0 (r%4==0)
        float4 v3 = make_float4(q3, q4, q5, q6);   // s=3 (r%4==1)
        float4 v2 = make_float4(q2, q3, q4, q5);   // s=2 (r%4==2)
        float4 v1 = make_float4(q1, q2, q3, q4);   // s=1 (r%4==3)

        // r = b*127 + t ≡ 3b + t (mod 4); r≡c ⇔ t ≡ c + b (mod 4)
        int t0;
        t0 = (0 + b) & 3;
        #pragma unroll 4
        for (int t = t0; t < T; t += 4) __stcs((float4*)(ob + (size_t)t * V + 4 * j + 0), v0);
        t0 = (1 + b) & 3;
        #pragma unroll 4
        for (int t = t0; t < T; t += 4) __stcs((float4*)(ob + (size_t)t * V + 4 * j + 3), v3);
        t0 = (2 + b) & 3;
        #pragma unroll 4
        for (int t = t0; t < T; t += 4) __stcs((float4*)(ob + (size_t)t * V + 4 * j + 2), v2);
        t0 = (3 + b) & 3;
        #pragma unroll 4
        for (int t = t0; t < T; t += 4) __stcs((float4*)(ob + (size_t)t * V + 4 * j + 1), v1);
    } else if (j == NQ) {
        h0 -= sub; h1 -= sub; h2 -= sub;
        e0 -= sub; e1 -= sub; e2 -= sub; e3 -= sub; e4 -= sub;
        for (int t = 0; t < T; t++) {
            int c = (3 * b + t) & 3;        // r & 3
            int sshift = (4 - c) & 3;
            float* row = ob + (size_t)t * V;
            if (sshift > 0) __stcs(row + 0, h0);
            if (sshift > 1) __stcs(row + 1, h1);
            if (sshift > 2) __stcs(row + 2, h2);
            if (sshift == 0) __stcs(row + 4 * NQ + 0, e0);
            if (sshift <= 1) __stcs(row + 4 * NQ + 1, e1);
            if (sshift <= 2) __stcs(row + 4 * NQ + 2, e2);
            if (sshift <= 3) __stcs(row + 4 * NQ + 3, e3);
            __stcs(row + 4 * NQ + 4, e4);
        }
    }
}

// ---------------------------------------------------------------------------
extern "C" void kernel_launch(void* const* d_in, const int* in_sizes, int n_in,
                              void* d_out, int out_size) {
    const int*   input    = (const int*)d_in[0];
    const float* hidden   = (const float*)d_in[1];
    const float* emb      = (const float*)d_in[2];
    const float* bridge_w = (const float*)d_in[3];
    const float* bridge_b = (const float*)d_in[4];
    const float* w_ih     = (const float*)d_in[5];
    const float* w_hh     = (const float*)d_in[6];
    const float* b_ih     = (const float*)d_in[7];
    const float* b_hh     = (const float*)d_in[8];
    const float* proj_w   = (const float*)d_in[9];
    const float* proj_b   = (const float*)d_in[10];
    float* out = (float*)d_out;

    const int k4_smem = 65536 + 32768;
    cudaFuncSetAttribute(k4_proj, cudaFuncAttributeMaxDynamicSharedMemorySize,
                         k4_smem);

    k123_front<<<NB123, 256>>>(input, hidden, emb, bridge_w, bridge_b,
                               w_ih, w_hh, b_ih, b_hh);
    int blocks4 = (V + 31) / 32;
    k4_proj<<<blocks4, 256, k4_smem>>>(proj_w, proj_b);
    dim3 g56(50, B);                      // 800 blocks total
    k56_out<<<g56, 256>>>(out);
}

// round 13
// speedup vs baseline: 1.0601x; 1.0468x over previous
#include <cuda_runtime.h>
#include <math.h>

#define B 16
#define L 128
#define H 1024
#define V 50257
#define T (L-1)
#define BP (B/2)
#define NQ 12563             // quads per row; 4*NQ = 50252
#define NB123 296            // fused front kernel: exactly 2 CTAs/SM x 148
#define NB56 800             // 50 x-blocks * 16 batches, co-resident (<=888)

typedef unsigned long long u64;

// ---- scratch (no allocations allowed) ----
__device__ float g_x0[B * H];
__device__ float g_h0[B * H];
__device__ float g_gi[B * 3 * H];
__device__ float g_gh[B * 3 * H];
__device__ float g_h1[B * H];
__device__ float g_logits[(size_t)B * V];
__device__ float g_sum[B];

// grid barrier state (generation counter -> graph-replay safe)
__device__ volatile unsigned g_bar_gen;
__device__ unsigned g_bar_cnt;

__device__ __forceinline__ void grid_barrier(int nblocks) {
    __syncthreads();
    if (threadIdx.x == 0) {
        unsigned gen = g_bar_gen;
        __threadfence();
        if (atomicAdd(&g_bar_cnt, 1) == (unsigned)(nblocks - 1)) {
            g_bar_cnt = 0;
            __threadfence();
            g_bar_gen = gen + 1;
        } else {
            while (g_bar_gen == gen) { }
        }
    }
    __syncthreads();
}

// packed f32x2 FMA: d = a*b + d (2 MACs / SASS FFMA2)
__device__ __forceinline__ void ffma2(u64 &d, u64 a, u64 b) {
    asm("fma.rn.f32x2 %0, %1, %2, %0;" : "+l"(d) : "l"(a), "l"(b));
}
__device__ __forceinline__ u64 dup2(float f) {
    u64 r;
    asm("mov.b64 %0, {%1, %1};" : "=l"(r) : "f"(f));
    return r;
}
__device__ __forceinline__ float lo2(u64 a) { return __uint_as_float((unsigned)a); }
__device__ __forceinline__ float hi2(u64 a) { return __uint_as_float((unsigned)(a >> 32)); }

// XOR swizzle on u64 index: flips the 16B-granule bit on alternating 128B lines
__device__ __forceinline__ int swz(int i) { return i ^ (((i >> 4) & 1) << 1); }

// cp.async 16B, L2-only path (streaming)
__device__ __forceinline__ void cpasync16(unsigned dst, const void* src) {
    asm volatile("cp.async.cg.shared.global [%0], [%1], 16;" :: "r"(dst), "l"(src) : "memory");
}
__device__ __forceinline__ void cpcommit() {
    asm volatile("cp.async.commit_group;" ::: "memory");
}
template <int N>
__device__ __forceinline__ void cpwait() {
    asm volatile("cp.async.wait_group %0;" :: "n"(N) : "memory");
}

// ---------------------------------------------------------------------------
// K123: fused embed+bridge -> barrier -> gates GEMV -> barrier -> GRU cell.
// 296 blocks (full 2-CTA/SM co-residency): balanced phase A (one iteration
// per block), guarded phase B. Zeroes g_sum for k56 atomics (replay-safe).
// ---------------------------------------------------------------------------
__global__ __launch_bounds__(256, 2)
void k123_front(const int* __restrict__ input,
                const float* __restrict__ hidden,
                const float* __restrict__ emb,
                const float* __restrict__ bridge_w,
                const float* __restrict__ bridge_b,
                const float* __restrict__ w_ih,
                const float* __restrict__ w_hh,
                const float* __restrict__ b_ih,
                const float* __restrict__ b_hh) {
    __shared__ float bw[L];
    __shared__ float part[4][64];
    int tid = threadIdx.x;
    if (tid < L) bw[tid] = bridge_w[tid];
    if (blockIdx.x == 0 && tid < B) g_sum[tid] = 0.f;
    __syncthreads();

    // ---- phase A: x0 = relu(emb[tok]); h0 = bridge(hidden) ----
    // 296*64 slots >= 16384 -> at most one iteration per block (balanced).
    int slot = tid & 63;
    int lc   = tid >> 6;
    int i0 = blockIdx.x * 64;
    if (i0 < B * H) {
        int i = i0 + slot;
        int b = i >> 10;
        int h = i & (H - 1);
        const float* hp = hidden + (size_t)b * L * H + (size_t)(lc * 32) * H + h;
        float a0 = 0.f, a1 = 0.f, a2 = 0.f, a3 = 0.f;
        #pragma unroll
        for (int l = 0; l < 32; l += 4) {
            a0 += __ldcs(hp + (l + 0) * H) * bw[lc * 32 + l + 0];
            a1 += __ldcs(hp + (l + 1) * H) * bw[lc * 32 + l + 1];
            a2 += __ldcs(hp + (l + 2) * H) * bw[lc * 32 + l + 2];
            a3 += __ldcs(hp + (l + 3) * H) * bw[lc * 32 + l + 3];
        }
        part[lc][slot] = (a0 + a1) + (a2 + a3);
        __syncthreads();
        if (lc == 0) {
            int tok = input[b * L];
            g_x0[i] = fmaxf(emb[(size_t)tok * H + h], 0.0f);
            g_h0[i] = (part[0][slot] + part[1][slot]) +
                      (part[2][slot] + part[3][slot]) + bridge_b[0];
        }
    }

    grid_barrier(NB123);

    // ---- phase B: gi = x0 @ w_ih^T + b_ih ; gh = h0 @ w_hh^T + b_hh ----
    {
        int warp = tid >> 5;
        int lane = tid & 31;
        int j0 = (blockIdx.x * 8 + warp) * 2;
        if (j0 < 3 * H) {
            float ai0[B], ai1[B], ah0[B], ah1[B];
            #pragma unroll
            for (int b = 0; b < B; b++) { ai0[b] = ai1[b] = ah0[b] = ah1[b] = 0.f; }

            for (int i = 0; i < 8; i++) {
                int k = i * 128 + lane * 4;
                float4 wi0 = *(const float4*)(w_ih + (size_t)(j0 + 0) * H + k);
                float4 wi1 = *(const float4*)(w_ih + (size_t)(j0 + 1) * H + k);
                float4 wh0 = *(const float4*)(w_hh + (size_t)(j0 + 0) * H + k);
                float4 wh1 = *(const float4*)(w_hh + (size_t)(j0 + 1) * H + k);
                #pragma unroll
                for (int b = 0; b < B; b++) {
                    float4 x = *(const float4*)(g_x0 + b * H + k);
                    float4 h = *(const float4*)(g_h0 + b * H + k);
                    ai0[b] += wi0.x * x.x + wi0.y * x.y + wi0.z * x.z + wi0.w * x.w;
                    ai1[b] += wi1.x * x.x + wi1.y * x.y + wi1.z * x.z + wi1.w * x.w;
                    ah0[b] += wh0.x * h.x + wh0.y * h.y + wh0.z * h.z + wh0.w * h.w;
                    ah1[b] += wh1.x * h.x + wh1.y * h.y + wh1.z * h.z + wh1.w * h.w;
                }
            }

            #pragma unroll
            for (int b = 0; b < B; b++) {
                #pragma unroll
                for (int o = 16; o; o >>= 1) {
                    ai0[b] += __shfl_xor_sync(0xffffffffu, ai0[b], o);
                    ai1[b] += __shfl_xor_sync(0xffffffffu, ai1[b], o);
                    ah0[b] += __shfl_xor_sync(0xffffffffu, ah0[b], o);
                    ah1[b] += __shfl_xor_sync(0xffffffffu, ah1[b], o);
                }
            }

            if (lane == 0) {
                float bi0 = b_ih[j0], bi1 = b_ih[j0 + 1];
                float bh0 = b_hh[j0], bh1 = b_hh[j0 + 1];
                #pragma unroll
                for (int b = 0; b < B; b++) {
                    g_gi[b * 3 * H + j0]     = ai0[b] + bi0;
                    g_gi[b * 3 * H + j0 + 1] = ai1[b] + bi1;
                    g_gh[b * 3 * H + j0]     = ah0[b] + bh0;
                    g_gh[b * 3 * H + j0 + 1] = ah1[b] + bh1;
                }
            }
        }
    }

    grid_barrier(NB123);

    // ---- phase C: GRU cell -> h1 ----
    {
        int gtid = blockIdx.x * 256 + tid;
        if (gtid < B * H) {
            int b = gtid >> 10;
            int h = gtid & (H - 1);
            int base = b * 3 * H + h;
            float ir = g_gi[base], iz = g_gi[base + H], in_ = g_gi[base + 2 * H];
            float hr = g_gh[base], hz = g_gh[base + H], hn  = g_gh[base + 2 * H];
            float r = 1.f / (1.f + expf(-(ir + hr)));
            float z = 1.f / (1.f + expf(-(iz + hz)));
            float n = tanhf(in_ + r * hn);
            g_h1[gtid] = (1.f - z) * n + z * g_h0[gtid];
        }
    }
}

// ---------------------------------------------------------------------------
// K4: logits[b,v] = h1[b,:] . proj_w[v,:] + proj_b[v]
// Batch-packed f32x2 + swizzled smem h1 + cp.async double-buffered proj_w.
// (committed version, unchanged)
// ---------------------------------------------------------------------------
__global__ __launch_bounds__(256, 2)
void k4_proj(const float* __restrict__ proj_w,
             const float* __restrict__ proj_b) {
    extern __shared__ char smem_raw[];
    u64*  hs = (u64*)smem_raw;                    // 64KB, swizzled
    char* pf = smem_raw + 65536;                  // 32KB staging

    for (int i = threadIdx.x; i < BP * H; i += 256) {
        int bp = i >> 10;
        int k  = i & (H - 1);
        unsigned lo = __float_as_uint(g_h1[(2 * bp) * H + k]);
        unsigned hi = __float_as_uint(g_h1[(2 * bp + 1) * H + k]);
        hs[swz(i)] = ((u64)hi << 32) | (u64)lo;
    }
    __syncthreads();

    int warp = threadIdx.x >> 5;
    int lane = threadIdx.x & 31;
    int v0 = (blockIdx.x * 8 + warp) * 4;
    if (v0 >= V) return;

    int r1 = min(v0 + 1, V - 1);
    int r2 = min(v0 + 2, V - 1);
    int r3 = min(v0 + 3, V - 1);
    const char* w0 = (const char*)(proj_w + (size_t)v0 * H);
    const char* w1 = (const char*)(proj_w + (size_t)r1 * H);
    const char* w2 = (const char*)(proj_w + (size_t)r2 * H);
    const char* w3 = (const char*)(proj_w + (size_t)r3 * H);

    char* pfw = pf + warp * 4096 + lane * 16;
    unsigned pfw_s = (unsigned)__cvta_generic_to_shared(pfw);

    u64 a0[BP], a1[BP], a2[BP], a3[BP];
    #pragma unroll
    for (int bp = 0; bp < BP; bp++) { a0[bp] = a1[bp] = a2[bp] = a3[bp] = 0ull; }

    {
        int off = lane * 16;
        cpasync16(pfw_s + 0 * 2048 + 0 * 512, w0 + off);
        cpasync16(pfw_s + 0 * 2048 + 1 * 512, w1 + off);
        cpasync16(pfw_s + 0 * 2048 + 2 * 512, w2 + off);
        cpasync16(pfw_s + 0 * 2048 + 3 * 512, w3 + off);
        cpcommit();
        cpasync16(pfw_s + 1 * 2048 + 0 * 512, w0 + 512 + off);
        cpasync16(pfw_s + 1 * 2048 + 1 * 512, w1 + 512 + off);
        cpasync16(pfw_s + 1 * 2048 + 2 * 512, w2 + 512 + off);
        cpasync16(pfw_s + 1 * 2048 + 3 * 512, w3 + 512 + off);
        cpcommit();
    }

    #pragma unroll
    for (int i = 0; i < 8; i++) {
        const int buf = i & 1;
        if (i < 6) cpwait<1>(); else cpwait<0>();

        const char* pb = pf + warp * 4096 + buf * 2048 + lane * 16;
        float4 p0 = *(const float4*)(pb + 0 * 512);
        float4 p1 = *(const float4*)(pb + 1 * 512);
        float4 p2 = *(const float4*)(pb + 2 * 512);
        float4 p3 = *(const float4*)(pb + 3 * 512);
        u64 q0x = dup2(p0.x), q0y = dup2(p0.y), q0z = dup2(p0.z), q0w = dup2(p0.w);
        u64 q1x = dup2(p1.x), q1y = dup2(p1.y), q1z = dup2(p1.z), q1w = dup2(p1.w);
        u64 q2x = dup2(p2.x), q2y = dup2(p2.y), q2z = dup2(p2.z), q2w = dup2(p2.w);
        u64 q3x = dup2(p3.x), q3y = dup2(p3.y), q3z = dup2(p3.z), q3w = dup2(p3.w);

        if (i < 6) {
            int off = (i + 2) * 512 + lane * 16;
            unsigned d = pfw_s + buf * 2048;
            cpasync16(d + 0 * 512, w0 + off);
            cpasync16(d + 1 * 512, w1 + off);
            cpasync16(d + 2 * 512, w2 + off);
            cpasync16(d + 3 * 512, w3 + off);
            cpcommit();
        }

        int kq = i * 32 + lane;
        #pragma unroll
        for (int bp = 0; bp < BP; bp++) {
            int idx = bp * 1024 + kq * 4;
            int f   = ((idx >> 4) & 1) << 1;
            ulonglong2 xa = *(const ulonglong2*)(hs + (idx ^ f));
            ulonglong2 xb = *(const ulonglong2*)(hs + ((idx + 2) ^ f));
            ffma2(a0[bp], q0x, xa.x); ffma2(a0[bp], q0y, xa.y);
            ffma2(a0[bp], q0z, xb.x); ffma2(a0[bp], q0w, xb.y);
            ffma2(a1[bp], q1x, xa.x); ffma2(a1[bp], q1y, xa.y);
            ffma2(a1[bp], q1z, xb.x); ffma2(a1[bp], q1w, xb.y);
            ffma2(a2[bp], q2x, xa.x); ffma2(a2[bp], q2y, xa.y);
            ffma2(a2[bp], q2z, xb.x); ffma2(a2[bp], q2w, xb.y);
            ffma2(a3[bp], q3x, xa.x); ffma2(a3[bp], q3y, xa.y);
            ffma2(a3[bp], q3z, xb.x); ffma2(a3[bp], q3w, xb.y);
        }
    }

    float pb0 = proj_b[v0];
    float pb1 = proj_b[r1];
    float pb2 = proj_b[r2];
    float pb3 = proj_b[r3];

    #pragma unroll
    for (int bp = 0; bp < BP; bp++) {
        float s0a = lo2(a0[bp]), s0b = hi2(a0[bp]);
        float s1a = lo2(a1[bp]), s1b = hi2(a1[bp]);
        float s2a = lo2(a2[bp]), s2b = hi2(a2[bp]);
        float s3a = lo2(a3[bp]), s3b = hi2(a3[bp]);
        #pragma unroll
        for (int o = 16; o; o >>= 1) {
            s0a += __shfl_xor_sync(0xffffffffu, s0a, o);
            s0b += __shfl_xor_sync(0xffffffffu, s0b, o);
            s1a += __shfl_xor_sync(0xffffffffu, s1a, o);
            s1b += __shfl_xor_sync(0xffffffffu, s1b, o);
            s2a += __shfl_xor_sync(0xffffffffu, s2a, o);
            s2b += __shfl_xor_sync(0xffffffffu, s2b, o);
            s3a += __shfl_xor_sync(0xffffffffu, s3a, o);
            s3b += __shfl_xor_sync(0xffffffffu, s3b, o);
        }
        if (lane == 0) {
            float* lga = g_logits + (size_t)(2 * bp) * V;
            float* lgb = g_logits + (size_t)(2 * bp + 1) * V;
            lga[v0] = s0a + pb0;  lgb[v0] = s0b + pb0;
            if (v0 + 1 < V) { lga[v0 + 1] = s1a + pb1;  lgb[v0 + 1] = s1b + pb1; }
            if (v0 + 2 < V) { lga[v0 + 2] = s2a + pb2;  lgb[v0 + 2] = s2b + pb2; }
            if (v0 + 3 < V) { lga[v0 + 3] = s3a + pb3;  lgb[v0 + 3] = s3b + pb3; }
        }
    }
}

// ---------------------------------------------------------------------------
// K56: fused log-sum-exp + broadcast output. (committed version, unchanged)
// ---------------------------------------------------------------------------
__global__ __launch_bounds__(256, 6)
void k56_out(float* __restrict__ out) {
    __shared__ float wsum[8];
    int j = blockIdx.x * 256 + threadIdx.x;
    int b = blockIdx.y;
    const float* lg = g_logits + (size_t)b * V;

    float q0 = 0, q1 = 0, q2 = 0, q3 = 0, q4 = 0, q5 = 0, q6 = 0;
    float h0 = 0, h1 = 0, h2 = 0, e0 = 0, e1 = 0, e2 = 0, e3 = 0, e4 = 0;
    float s = 0.f;
    if (j < NQ) {
        q0 = lg[4 * j + 0]; q1 = lg[4 * j + 1];
        q2 = lg[4 * j + 2]; q3 = lg[4 * j + 3];
        q4 = lg[4 * j + 4]; q5 = lg[4 * j + 5];
        q6 = lg[4 * j + 6];
        s = (expf(q0) + expf(q1)) + (expf(q2) + expf(q3));
    } else if (j == NQ) {
        h0 = lg[0]; h1 = lg[1]; h2 = lg[2];
        e0 = lg[4 * NQ + 0]; e1 = lg[4 * NQ + 1]; e2 = lg[4 * NQ + 2];
        e3 = lg[4 * NQ + 3]; e4 = lg[4 * NQ + 4];
        s = (expf(e0) + expf(e1)) + (expf(e2) + expf(e3)) + expf(e4);
    }

    #pragma unroll
    for (int o = 16; o; o >>= 1) s += __shfl_xor_sync(0xffffffffu, s, o);
    if ((threadIdx.x & 31) == 0) wsum[threadIdx.x >> 5] = s;
    __syncthreads();
    if (threadIdx.x == 0) {
        float t = 0.f;
        #pragma unroll
        for (int w = 0; w < 8; w++) t += wsum[w];
        atomicAdd(&g_sum[b], t);
    }

    grid_barrier(NB56);

    float sub = logf(__ldcg((const float*)&g_sum[b]));
    float* ob = out + (size_t)b * T * V;

    if (j < NQ) {
        q0 -= sub; q1 -= sub; q2 -= sub; q3 -= sub;
        q4 -= sub; q5 -= sub; q6 -= sub;
        float4 v0 = make_float4(q0, q1, q2, q3);   // s=0 (r%4==0)
        float4 v3 = make_float4(q3, q4, q5, q6);   // s=3 (r%4==1)
        float4 v2 = make_float4(q2, q3, q4, q5);   // s=2 (r%4==2)
        float4 v1 = make_float4(q1, q2, q3, q4);   // s=1 (r%4==3)

        int t0;
        t0 = (0 + b) & 3;
        #pragma unroll 4
        for (int t = t0; t < T; t += 4) __stcs((float4*)(ob + (size_t)t * V + 4 * j + 0), v0);
        t0 = (1 + b) & 3;
        #pragma unroll 4
        for (int t = t0; t < T; t += 4) __stcs((float4*)(ob + (size_t)t * V + 4 * j + 3), v3);
        t0 = (2 + b) & 3;
        #pragma unroll 4
        for (int t = t0; t < T; t += 4) __stcs((float4*)(ob + (size_t)t * V + 4 * j + 2), v2);
        t0 = (3 + b) & 3;
        #pragma unroll 4
        for (int t = t0; t < T; t += 4) __stcs((float4*)(ob + (size_t)t * V + 4 * j + 1), v1);
    } else if (j == NQ) {
        h0 -= sub; h1 -= sub; h2 -= sub;
        e0 -= sub; e1 -= sub; e2 -= sub; e3 -= sub; e4 -= sub;
        for (int t = 0; t < T; t++) {
            int c = (3 * b + t) & 3;        // r & 3
            int sshift = (4 - c) & 3;
            float* row = ob + (size_t)t * V;
            if (sshift > 0) __stcs(row + 0, h0);
            if (sshift > 1) __stcs(row + 1, h1);
            if (sshift > 2) __stcs(row + 2, h2);
            if (sshift == 0) __stcs(row + 4 * NQ + 0, e0);
            if (sshift <= 1) __stcs(row + 4 * NQ + 1, e1);
            if (sshift <= 2) __stcs(row + 4 * NQ + 2, e2);
            if (sshift <= 3) __stcs(row + 4 * NQ + 3, e3);
            __stcs(row + 4 * NQ + 4, e4);
        }
    }
}

// ---------------------------------------------------------------------------
extern "C" void kernel_launch(void* const* d_in, const int* in_sizes, int n_in,
                              void* d_out, int out_size) {
    const int*   input    = (const int*)d_in[0];
    const float* hidden   = (const float*)d_in[1];
    const float* emb      = (const float*)d_in[2];
    const float* bridge_w = (const float*)d_in[3];
    const float* bridge_b = (const float*)d_in[4];
    const float* w_ih     = (const float*)d_in[5];
    const float* w_hh     = (const float*)d_in[6];
    const float* b_ih     = (const float*)d_in[7];
    const float* b_hh     = (const float*)d_in[8];
    const float* proj_w   = (const float*)d_in[9];
    const float* proj_b   = (const float*)d_in[10];
    float* out = (float*)d_out;

    const int k4_smem = 65536 + 32768;
    cudaFuncSetAttribute(k4_proj, cudaFuncAttributeMaxDynamicSharedMemorySize,
                         k4_smem);

    k123_front<<<NB123, 256>>>(input, hidden, emb, bridge_w, bridge_b,
                               w_ih, w_hh, b_ih, b_hh);
    int blocks4 = (V + 31) / 32;
    k4_proj<<<blocks4, 256, k4_smem>>>(proj_w, proj_b);
    dim3 g56(50, B);                      // 800 blocks total
    k56_out<<<g56, 256>>>(out);
}